// round 16
// baseline (speedup 1.0000x reference)
#include <cuda_runtime.h>
#include <cuda_fp16.h>
#include <math.h>

#define D_    128
#define H_    8
#define DK_   16
#define T_    3
#define R_    4
#define MAXN  50048
#define MAXE  800000
#define PERM_SZ 50432   // fits n + 3*127, 128-aligned
#define NCHUNK 64

// ------------------------- device scratch -------------------------
// Combined GEMM weights: [t][1152 outs][128 in] fp16. Outs: [k(128) | qt r0..3 (512) | mt r0..3 (512)]
static __device__ __align__(16) __half g_W2[3*1152*128];
static __device__ __align__(16) float  g_b2[3*1152];
static __device__ __align__(16) float  g_Wf[2*3*16384];   // WeffqT, WeffvT fp32 [t][o][d]  (TRANSPOSED)
static __device__ __align__(16) float  g_bqv[2*3*128];    // bq_eff, bv_eff
static __device__ __align__(16) float  g_A [R_*H_*DK_*DK_]; // [r][h][d][o]
static __device__ __align__(16) float  g_M [R_*H_*DK_*DK_];
static __device__ float g_pri4[R_*H_];
static __device__ __align__(16) __half g_Wup_h[3*16384];  // [t][o][d] transposed fp16
static __device__ __align__(16) __half g_x_h [MAXN*D_];
static __device__ __align__(16) __half g_k_h [MAXN*D_];
static __device__ __align__(16) __half g_qt_h[MAXN*R_*D_]; // [n][r][h][d] pri-scaled
static __device__ __align__(16) __half g_mt_h[MAXN*R_*D_]; // [n][r][h][o]
static __device__ __align__(16) __half g_ge_h[MAXN*D_];    // half(gelu(attn))
static __device__ int g_deg[MAXN];
static __device__ int g_rowoff[MAXN+1];   // FINAL offsets after scan
static __device__ int g_pos[MAXE];        // per-edge within-node position (from count)
static __device__ int g_bflagsum[NCHUNK]; // chunk total + 1 (0 = not ready)
static __device__ int g_se[MAXE];          // (src<<2)|rel
static __device__ int g_perm[PERM_SZ];
static __device__ int g_tcount[8];
static __device__ int g_ncursor[8];
static __device__ int g_toff[8];

// ------------------------- helpers -------------------------
__device__ __forceinline__ void softmax2(float a0, float a1, float &o0, float &o1){
    float m  = fmaxf(a0, a1);
    float e0 = __expf(a0 - m), e1 = __expf(a1 - m);
    float inv = 1.0f / (e0 + e1);
    o0 = e0 * inv; o1 = e1 * inv;
}

__device__ __forceinline__ float gelu_t(float x){
    float x3 = x * x * x;
    return 0.5f * x * (1.0f + tanhf(0.7978845608028654f * (x + 0.044715f * x3)));
}

__device__ __forceinline__ void mma16816(float c[4], unsigned a0, unsigned a1,
                                         unsigned a2, unsigned a3,
                                         unsigned b0, unsigned b1){
    asm volatile(
        "mma.sync.aligned.m16n8k16.row.col.f32.f16.f16.f32 "
        "{%0,%1,%2,%3}, {%4,%5,%6,%7}, {%8,%9}, {%0,%1,%2,%3};"
        : "+f"(c[0]), "+f"(c[1]), "+f"(c[2]), "+f"(c[3])
        : "r"(a0), "r"(a1), "r"(a2), "r"(a3), "r"(b0), "r"(b1));
}

__device__ __forceinline__ void ldsm_x4(unsigned &r0, unsigned &r1,
                                        unsigned &r2, unsigned &r3, unsigned addr){
    asm volatile("ldmatrix.sync.aligned.m8n8.x4.shared.b16 {%0,%1,%2,%3}, [%4];"
        : "=r"(r0), "=r"(r1), "=r"(r2), "=r"(r3) : "r"(addr));
}

// ------------------------- fused init + x->fp16 + weights ---------
__global__ void fused_init_kernel(const float* __restrict__ x,
                            const float* __restrict__ Wk, const float* __restrict__ bk,
                            const float* __restrict__ Wq, const float* __restrict__ bq,
                            const float* __restrict__ Wv, const float* __restrict__ bv,
                            const float* __restrict__ rel_pri,
                            const float* __restrict__ rel_att,
                            const float* __restrict__ rel_msg,
                            const float* __restrict__ n_alpha,
                            const float* __restrict__ r_alpha,
                            const float* __restrict__ W_up,
                            int n, int n32){
    int g = blockIdx.x * blockDim.x + threadIdx.x;
    const int NW = 3*16384;   // 49152
    const int NB = 9*128;
    const int NA = R_*H_*256; // 8192

    if (g < n32){
        float4 v = ((const float4*)x)[g];
        __half2 h0 = __floats2half2_rn(v.x, v.y);
        __half2 h1 = __floats2half2_rn(v.z, v.w);
        ((uint2*)g_x_h)[g] = make_uint2(*(unsigned*)&h0, *(unsigned*)&h1);
        return;
    }
    g -= n32;
    if (g < NW){   // Weff_k -> g_W2 [t][o][d] fp16 (transposed)
        int t = g / 16384, j = g % 16384;
        int d = j >> 7, o = j & 127;
        float a0, a1; softmax2(n_alpha[t*2], n_alpha[t*2+1], a0, a1);
        g_W2[(t*1152 + o)*128 + d] = __float2half_rn(a0*Wk[j] + a1*Wk[16384 + j]);
        return;
    }
    g -= NW;
    if (g < NW){   // WeffqT fp32 [t][o][d]
        int t = g / 16384, rem = g % 16384;
        int o = rem >> 7, d = rem & 127;
        float a0, a1; softmax2(n_alpha[t*2], n_alpha[t*2+1], a0, a1);
        g_Wf[t*16384 + o*128 + d] = a0*Wq[d*128 + o] + a1*Wq[16384 + d*128 + o];
        return;
    }
    g -= NW;
    if (g < NW){   // WeffvT fp32 [t][o][d]
        int t = g / 16384, rem = g % 16384;
        int o = rem >> 7, d = rem & 127;
        float a0, a1; softmax2(n_alpha[t*2], n_alpha[t*2+1], a0, a1);
        g_Wf[3*16384 + t*16384 + o*128 + d] = a0*Wv[d*128 + o] + a1*Wv[16384 + d*128 + o];
        return;
    }
    g -= NW;
    if (g < NW){   // W_up transposed fp16
        int t = g / 16384, j = g % 16384;
        int d = j >> 7, o = j & 127;
        g_Wup_h[t*16384 + o*128 + d] = __float2half_rn(W_up[t*16384 + j]);
        return;
    }
    g -= NW;
    if (g < NB){
        int m = g / 384, rem = g % 384, t = rem / 128, c = rem % 128;
        float a0, a1; softmax2(n_alpha[t*2], n_alpha[t*2+1], a0, a1);
        const float* B = (m==0) ? bk : (m==1) ? bq : bv;
        float val = a0*B[c] + a1*B[128 + c];
        if (m == 0) g_b2[t*1152 + c] = val;
        else        g_bqv[((m-1)*3 + t)*128 + c] = val;
        return;
    }
    g -= NB;
    if (g < NA){
        int r = g / 2048, j = g % 2048;
        float b0, b1; softmax2(r_alpha[r*2], r_alpha[r*2+1], b0, b1);
        g_A[g] = b0*rel_att[j] + b1*rel_att[2048 + j];
        return;
    }
    g -= NA;
    if (g < NA){
        int r = g / 2048, j = g % 2048;
        float b0, b1; softmax2(r_alpha[r*2], r_alpha[r*2+1], b0, b1);
        g_M[g] = b0*rel_msg[j] + b1*rel_msg[2048 + j];
        return;
    }
    g -= NA;
    if (g < 32){
        int r = g/8, h = g%8;
        float b0, b1; softmax2(r_alpha[r*2], r_alpha[r*2+1], b0, b1);
        g_pri4[g] = (b0*rel_pri[h] + b1*rel_pri[8 + h]) * 0.25f;
        return;
    }
    g -= 32;
    if (g < n){ g_deg[g] = 0; return; }
    g -= n;
    if (g < PERM_SZ){ g_perm[g] = -1; return; }
    g -= PERM_SZ;
    if (g < 8){ g_tcount[g] = 0; g_ncursor[g] = 0; return; }
    g -= 8;
    if (g < NCHUNK) g_bflagsum[g] = 0;
}

// -- prep2: W2 qt/mt + folded biases + COUNT (positions saved) -----
__global__ void prep2_kernel(const int* __restrict__ ei, const int* __restrict__ ntype,
                             int n, int e){
    int g = blockIdx.x * blockDim.x + threadIdx.x;
    const int NW2 = 3*1024*128;  // 393216
    if (g < NW2){
        int t = g / 131072, rem = g % 131072;
        int col = rem >> 7, d = rem & 127;
        int part = col >> 9;
        int c = col & 511;
        int r = c >> 7, ho = c & 127, h = ho >> 4, j = ho & 15;
        const float* tab = part ? g_M : g_A;
        const float* Wf  = g_Wf + (part*3 + t)*16384 + (h*16)*128 + d;  // step 128 per i
        const float* ta  = tab + r*2048 + h*256 + (part ? j : j*16);
        int st = part ? 16 : 1;
        float s = 0.f;
        #pragma unroll
        for (int i = 0; i < 16; i++) s += ta[i*st] * Wf[i*128];
        if (!part) s *= g_pri4[r*8 + h];
        g_W2[(t*1152 + 128 + col)*128 + d] = __float2half_rn(s);
        return;
    }
    g -= NW2;
    if (g < 3072){
        int t = g / 1024, col = g % 1024;
        int part = col >> 9;
        int c = col & 511;
        int r = c >> 7, ho = c & 127, h = ho >> 4, j = ho & 15;
        const float* tab = part ? g_M : g_A;
        const float* bv  = g_bqv + (part*3 + t)*128 + h*16;
        const float* ta  = tab + r*2048 + h*256 + (part ? j : j*16);
        int st = part ? 16 : 1;
        float s = 0.f;
        #pragma unroll
        for (int i = 0; i < 16; i++) s += ta[i*st] * bv[i];
        if (!part) s *= g_pri4[r*8 + h];
        g_b2[t*1152 + 128 + col] = s;
        return;
    }
    g -= 3072;
    // ---- merged count: positions saved for atomic-free scatter ----
    int ecnt4 = (e + 3) >> 2;
    if (g < ecnt4){
        int g4 = g * 4;
        if (g4 + 3 < e){
            int4 d = *(const int4*)&ei[e + g4];
            int4 p;
            p.x = atomicAdd(&g_deg[d.x], 1);
            p.y = atomicAdd(&g_deg[d.y], 1);
            p.z = atomicAdd(&g_deg[d.z], 1);
            p.w = atomicAdd(&g_deg[d.w], 1);
            *(int4*)&g_pos[g4] = p;
        } else {
            for (int i = g4; i < e; i++) g_pos[i] = atomicAdd(&g_deg[ei[e + i]], 1);
        }
        unsigned act = __activemask();
        int lane = threadIdx.x & 31;
        #pragma unroll
        for (int j = 0; j < 4; j++){
            int i = g4 + j;
            int t = (i < n) ? ntype[i] : -1;
            unsigned mask = __match_any_sync(act, t);
            if (t >= 0){
                int leader = __ffs(mask) - 1;
                if (lane == leader) atomicAdd(&g_tcount[t], __popc(mask));
            }
        }
    }
}

// ---- single-pass scan with decoupled lookback, FINAL offsets -----
__global__ void scan_kernel(int nb, int n){
    __shared__ int wsum[32];
    __shared__ int chunkpref;
    int tid = threadIdx.x, lane = tid & 31, wid = tid >> 5;
    int b = blockIdx.x;
    int i = b * 1024 + tid;
    int v = (i < n) ? g_deg[i] : 0;
    int x = v;
    #pragma unroll
    for (int o = 1; o < 32; o <<= 1){
        int y = __shfl_up_sync(0xffffffffu, x, o);
        if (lane >= o) x += y;
    }
    if (lane == 31) wsum[wid] = x;
    __syncthreads();
    if (wid == 0){
        int s = wsum[lane];
        #pragma unroll
        for (int o = 1; o < 32; o <<= 1){
            int y = __shfl_up_sync(0xffffffffu, s, o);
            if (lane >= o) s += y;
        }
        wsum[lane] = s;
    }
    __syncthreads();
    int pre = (wid > 0) ? wsum[wid-1] : 0;
    int total = wsum[31];
    if (tid == 0) atomicExch(&g_bflagsum[b], total + 1);   // publish
    if (wid == 0){
        int mysum = 0;
        for (int j = lane; j < b; j += 32){
            int val;
            do { val = atomicAdd(&g_bflagsum[j], 0); } while (val == 0);
            mysum += val - 1;
        }
        #pragma unroll
        for (int o = 16; o > 0; o >>= 1)
            mysum += __shfl_xor_sync(0xffffffffu, mysum, o);
        if (lane == 0){
            chunkpref = mysum;
            if (b == nb - 1){
                g_rowoff[n] = mysum + total;
                g_toff[0] = 0;
                for (int t = 0; t < T_; t++)
                    g_toff[t+1] = g_toff[t] + ((g_tcount[t] + 127) & ~127);
            }
        }
    }
    __syncthreads();
    int cp = chunkpref;
    if (i < n) g_rowoff[i] = cp + pre + x - v;   // FINAL exclusive offset
}

// ------------- scatter: atomic-free via saved positions -----------
__global__ void scatter_kernel(const int* __restrict__ ei, const int* __restrict__ etype,
                               const int* __restrict__ ntype, int n, int e){
    int g4 = (blockIdx.x * 256 + threadIdx.x) * 4;
    if (g4 + 3 < e){
        int4 s = *(const int4*)&ei[g4];
        int4 d = *(const int4*)&ei[e + g4];
        int4 r = *(const int4*)&etype[g4];
        int4 p = *(const int4*)&g_pos[g4];
        g_se[g_rowoff[d.x] + p.x] = (s.x << 2) | r.x;
        g_se[g_rowoff[d.y] + p.y] = (s.y << 2) | r.y;
        g_se[g_rowoff[d.z] + p.z] = (s.z << 2) | r.z;
        g_se[g_rowoff[d.w] + p.w] = (s.w << 2) | r.w;
    } else if (g4 < e){
        for (int i = g4; i < e; i++){
            int d = ei[e + i];
            g_se[g_rowoff[d] + g_pos[i]] = (ei[i] << 2) | etype[i];
        }
    }
    int lane = threadIdx.x & 31;
    #pragma unroll
    for (int j = 0; j < 4; j++){
        int i = g4 + j;
        int t = (i < n) ? ntype[i] : 3;
        unsigned mask = __match_any_sync(0xffffffffu, t);
        if (i < n){
            int leader = __ffs(mask) - 1;
            int rank = __popc(mask & ((1u << lane) - 1));
            int base = 0;
            if (lane == leader) base = atomicAdd(&g_ncursor[t], __popc(mask));
            base = __shfl_sync(mask, base, leader);
            g_perm[g_toff[t] + base + rank] = i;
        }
    }
}

// ---- GEMM: x -> k|qt|mt (64-row tiles, ldmatrix, 3 blocks/SM) ----
__global__ void __launch_bounds__(256, 3) gemm_kernel(){
    int my = blockIdx.y;
    int base = blockIdx.x * 64;
    if (base >= g_toff[3]) return;
    int t = (base >= g_toff[2]) ? 2 : (base >= g_toff[1]) ? 1 : 0;
    const __half* __restrict__ W  = g_W2 + (t*1152 + my*128)*128;
    const float* __restrict__ bvec = g_b2 + t*1152 + my*128;

    __shared__ __half Xs[64][72];
    __shared__ __half Wt[128][72];
    __shared__ int rows[64];
    __shared__ float bs[128];

    int tid = threadIdx.x;
    if (tid < 64) rows[tid] = g_perm[base + tid];
    if (tid >= 128) bs[tid-128] = bvec[tid-128];
    __syncthreads();

    int lane = tid & 31, wid = tid >> 5;
    int wm = wid & 3, wn = wid >> 2;
    float acc[8][4] = {};

    // ldmatrix per-lane addresses (constant across kp; add kk*2 bytes)
    int l7 = lane & 7;
    int arow_off = l7 + ((lane >> 3) & 1) * 8;      // rows 0-15 of A tile
    int acol_off = (lane >> 4) * 8;                  // k quadrant 0 or 8
    unsigned aBase = (unsigned)__cvta_generic_to_shared(&Xs[wm*16 + arow_off][acol_off]);
    int brow_off = l7 + ((lane >> 4) ? 8 : 0);       // n rows 0-15 of pair
    int bcol_off = ((lane >> 3) & 1) * 8;            // k quadrant
    unsigned bBase[4];
    #pragma unroll
    for (int p = 0; p < 4; p++)
        bBase[p] = (unsigned)__cvta_generic_to_shared(&Wt[wn*64 + p*16 + brow_off][bcol_off]);

    for (int kp = 0; kp < 128; kp += 64){
        if (kp) __syncthreads();
        for (int c = tid; c < 512; c += 256){
            int row = c >> 3, cg = c & 7;
            int nd = rows[row];
            uint4 v = (nd >= 0) ? *(const uint4*)&g_x_h[nd*128 + kp + cg*8]
                                : make_uint4(0,0,0,0);
            *(uint4*)&Xs[row][cg*8] = v;
        }
        for (int c = tid; c < 1024; c += 256){
            int row = c >> 3, cg = c & 7;
            *(uint4*)&Wt[row][cg*8] = *(const uint4*)&W[row*128 + kp + cg*8];
        }
        __syncthreads();
        #pragma unroll
        for (int kk = 0; kk < 64; kk += 16){
            unsigned a[4], bb[4][4];
            ldsm_x4(a[0], a[1], a[2], a[3], aBase + kk*2);
            #pragma unroll
            for (int p = 0; p < 4; p++)
                ldsm_x4(bb[p][0], bb[p][1], bb[p][2], bb[p][3], bBase[p] + kk*2);
            #pragma unroll
            for (int nt = 0; nt < 8; nt++){
                unsigned b0 = bb[nt>>1][(nt&1)*2];
                unsigned b1 = bb[nt>>1][(nt&1)*2 + 1];
                mma16816(acc[nt], a[0], a[1], a[2], a[3], b0, b1);
            }
        }
    }

    __half* outb; int stride;
    if (my == 0){ outb = g_k_h; stride = 128; }
    else if (my < 5){ outb = g_qt_h + (my-1)*128; stride = 512; }
    else { outb = g_mt_h + (my-5)*128; stride = 512; }

    int gq = lane >> 2, tig = lane & 3;
    #pragma unroll
    for (int nt = 0; nt < 8; nt++){
        int col = wn*64 + nt*8 + tig*2;
        float b0 = bs[col], b1 = bs[col+1];
        #pragma unroll
        for (int rr = 0; rr < 2; rr++){
            int row = wm*16 + gq + rr*8;
            int nd = rows[row];
            if (nd < 0) continue;
            __half2 h2 = __floats2half2_rn(acc[nt][rr*2] + b0,
                                           acc[nt][rr*2+1] + b1);
            *(__half2*)&outb[nd*stride + col] = h2;
        }
    }
}

// ------------------------- edge: warp/dst, no-max softmax ---------
__global__ void __launch_bounds__(256) edge_kernel(int n){
    int node = blockIdx.x*8 + (threadIdx.x >> 5);
    if (node >= n) return;
    int lane = threadIdx.x & 31;
    int h = lane >> 2, dq = lane & 3;
    int koff = h*16 + dq*4;

    float4 qt[4];
    #pragma unroll
    for (int r = 0; r < 4; r++){
        uint2 qa = *(const uint2*)&g_qt_h[node*512 + r*128 + koff];
        float2 lo = __half22float2(*(__half2*)&qa.x);
        float2 hi = __half22float2(*(__half2*)&qa.y);
        qt[r] = make_float4(lo.x, lo.y, hi.x, hi.y);
    }

    int beg = g_rowoff[node], end = g_rowoff[node+1];
    float s = 0.f;
    float4 acc = {0,0,0,0};

    int se0 = 0, se1 = 0;
    uint2 k0 = {0,0}, k1 = {0,0}, mm0 = {0,0}, mm1 = {0,0};
    if (beg < end){
        se0 = g_se[beg]; int sr = se0 >> 2, r = se0 & 3;
        k0  = *(const uint2*)&g_k_h [sr*128 + koff];
        mm0 = *(const uint2*)&g_mt_h[sr*512 + r*128 + koff];
    }
    if (beg + 1 < end){
        se1 = g_se[beg+1]; int sr = se1 >> 2, r = se1 & 3;
        k1  = *(const uint2*)&g_k_h [sr*128 + koff];
        mm1 = *(const uint2*)&g_mt_h[sr*512 + r*128 + koff];
    }

    for (int o = beg; o < end; o += 2){
        int nse0 = 0, nse1 = 0;
        uint2 nk0 = {0,0}, nk1 = {0,0}, nm0 = {0,0}, nm1 = {0,0};
        if (o + 2 < end){
            nse0 = g_se[o+2]; int sr = nse0 >> 2, r = nse0 & 3;
            nk0 = *(const uint2*)&g_k_h [sr*128 + koff];
            nm0 = *(const uint2*)&g_mt_h[sr*512 + r*128 + koff];
        }
        if (o + 3 < end){
            nse1 = g_se[o+3]; int sr = nse1 >> 2, r = nse1 & 3;
            nk1 = *(const uint2*)&g_k_h [sr*128 + koff];
            nm1 = *(const uint2*)&g_mt_h[sr*512 + r*128 + koff];
        }
        {
            int r = se0 & 3;
            float2 ka = __half22float2(*(__half2*)&k0.x);
            float2 kb = __half22float2(*(__half2*)&k0.y);
            float4 q4 = qt[r];
            float p = ka.x*q4.x + ka.y*q4.y + kb.x*q4.z + kb.y*q4.w;
            p += __shfl_xor_sync(0xffffffffu, p, 1);
            p += __shfl_xor_sync(0xffffffffu, p, 2);
            float e = __expf(fminf(p, 60.f));
            float2 ma = __half22float2(*(__half2*)&mm0.x);
            float2 mb = __half22float2(*(__half2*)&mm0.y);
            s += e;
            acc.x += e*ma.x; acc.y += e*ma.y;
            acc.z += e*mb.x; acc.w += e*mb.y;
        }
        if (o + 1 < end){
            int r = se1 & 3;
            float2 ka = __half22float2(*(__half2*)&k1.x);
            float2 kb = __half22float2(*(__half2*)&k1.y);
            float4 q4 = qt[r];
            float p = ka.x*q4.x + ka.y*q4.y + kb.x*q4.z + kb.y*q4.w;
            p += __shfl_xor_sync(0xffffffffu, p, 1);
            p += __shfl_xor_sync(0xffffffffu, p, 2);
            float e = __expf(fminf(p, 60.f));
            float2 ma = __half22float2(*(__half2*)&mm1.x);
            float2 mb = __half22float2(*(__half2*)&mm1.y);
            s += e;
            acc.x += e*ma.x; acc.y += e*ma.y;
            acc.z += e*mb.x; acc.w += e*mb.y;
        }
        se0 = nse0; k0 = nk0; mm0 = nm0;
        se1 = nse1; k1 = nk1; mm1 = nm1;
    }
    float inv = 1.0f / (s + 1e-16f);
    __half2 h0 = __floats2half2_rn(gelu_t(acc.x*inv), gelu_t(acc.y*inv));
    __half2 h1 = __floats2half2_rn(gelu_t(acc.z*inv), gelu_t(acc.w*inv));
    *(uint2*)&g_ge_h[node*128 + koff] = make_uint2(*(unsigned*)&h0, *(unsigned*)&h1);
}

// ------------------------- tensor-core update + residual + LN -----
__global__ void __launch_bounds__(256) update_tc_kernel(
        const float* __restrict__ x, const float* __restrict__ bup,
        const float* __restrict__ gamma, const float* __restrict__ beta,
        float* __restrict__ out){
    int base = blockIdx.x * 64;
    if (base >= g_toff[3]) return;
    int t = (base >= g_toff[2]) ? 2 : (base >= g_toff[1]) ? 1 : 0;
    const __half* __restrict__ W = g_Wup_h + t*16384;

    __shared__ union {
        struct { __half Xs[64][136]; __half Wt[128][72]; } s;
        float Cs[64][132];
    } u;
    __shared__ int rows[64];
    __shared__ float bs[128];

    int tid = threadIdx.x;
    if (tid < 64) rows[tid] = g_perm[base + tid];
    if (tid >= 128 && tid < 256) bs[tid-128] = bup[t*128 + tid-128];
    __syncthreads();

    for (int c = tid; c < 1024; c += 256){
        int row = c >> 4, cg = c & 15;
        int nd = rows[row];
        uint4 v = (nd >= 0) ? *(const uint4*)&g_ge_h[nd*128 + cg*8]
                            : make_uint4(0,0,0,0);
        *(uint4*)&u.s.Xs[row][cg*8] = v;
    }

    int lane = tid & 31, wid = tid >> 5;
    int wm = wid & 3, wn = wid >> 2;
    int gq = lane >> 2, tig = lane & 3;
    float acc[8][4] = {};

    for (int kp = 0; kp < 128; kp += 64){
        __syncthreads();
        for (int c = tid; c < 1024; c += 256){
            int nrow = c >> 3, cg = c & 7;
            *(uint4*)&u.s.Wt[nrow][cg*8] = *(const uint4*)&W[nrow*128 + kp + cg*8];
        }
        __syncthreads();
        #pragma unroll
        for (int kk = 0; kk < 64; kk += 16){
            int arow = wm*16 + gq;
            int acol = kp + kk + tig*2;
            unsigned a0 = *(unsigned*)&u.s.Xs[arow][acol];
            unsigned a1 = *(unsigned*)&u.s.Xs[arow+8][acol];
            unsigned a2 = *(unsigned*)&u.s.Xs[arow][acol+8];
            unsigned a3 = *(unsigned*)&u.s.Xs[arow+8][acol+8];
            #pragma unroll
            for (int nt = 0; nt < 8; nt++){
                int brow = wn*64 + nt*8 + gq;
                unsigned b0 = *(unsigned*)&u.s.Wt[brow][kk + tig*2];
                unsigned b1 = *(unsigned*)&u.s.Wt[brow][kk + 8 + tig*2];
                mma16816(acc[nt], a0, a1, a2, a3, b0, b1);
            }
        }
    }
    __syncthreads();
    #pragma unroll
    for (int nt = 0; nt < 8; nt++){
        int col = wn*64 + nt*8 + tig*2;
        float b0 = bs[col], b1 = bs[col+1];
        #pragma unroll
        for (int rr = 0; rr < 2; rr++){
            int row = wm*16 + gq + rr*8;
            u.Cs[row][col]   = acc[nt][rr*2]   + b0;
            u.Cs[row][col+1] = acc[nt][rr*2+1] + b1;
        }
    }
    __syncthreads();

    int tx = tid & 31, ty = tid >> 5;
    float4 g4 = *(const float4*)&gamma[t*128 + tx*4];
    float4 e4 = *(const float4*)&beta [t*128 + tx*4];
    #pragma unroll
    for (int i = 0; i < 8; i++){
        int row = ty*8 + i;
        int nd = rows[row];
        if (nd < 0) continue;
        float4 cv = *(float4*)&u.Cs[row][tx*4];
        float4 xi = *(const float4*)&x[nd*128 + tx*4];
        float v0 = cv.x + xi.x, v1 = cv.y + xi.y;
        float v2 = cv.z + xi.z, v3 = cv.w + xi.w;
        float sum = v0+v1+v2+v3;
        float sq  = v0*v0+v1*v1+v2*v2+v3*v3;
        #pragma unroll
        for (int o = 16; o > 0; o >>= 1){
            sum += __shfl_xor_sync(0xffffffffu, sum, o);
            sq  += __shfl_xor_sync(0xffffffffu, sq,  o);
        }
        float mu = sum * (1.0f/128.0f);
        float var = sq * (1.0f/128.0f) - mu*mu;
        float rstd = rsqrtf(var + 1e-5f);
        float4 o4;
        o4.x = (v0-mu)*rstd*g4.x + e4.x;
        o4.y = (v1-mu)*rstd*g4.y + e4.y;
        o4.z = (v2-mu)*rstd*g4.z + e4.z;
        o4.w = (v3-mu)*rstd*g4.w + e4.w;
        *(float4*)&out[nd*128 + tx*4] = o4;
    }
}

// ------------------------- launch ---------------------------------
extern "C" void kernel_launch(void* const* d_in, const int* in_sizes, int n_in,
                              void* d_out, int out_size) {
    const float* x       = (const float*)d_in[0];
    const float* Wk      = (const float*)d_in[1];
    const float* bk      = (const float*)d_in[2];
    const float* Wq      = (const float*)d_in[3];
    const float* bq      = (const float*)d_in[4];
    const float* Wv      = (const float*)d_in[5];
    const float* bv      = (const float*)d_in[6];
    const float* rel_pri = (const float*)d_in[7];
    const float* rel_att = (const float*)d_in[8];
    const float* rel_msg = (const float*)d_in[9];
    const float* n_alpha = (const float*)d_in[10];
    const float* r_alpha = (const float*)d_in[11];
    const float* W_up    = (const float*)d_in[12];
    const float* b_up    = (const float*)d_in[13];
    const float* gamma   = (const float*)d_in[14];
    const float* beta    = (const float*)d_in[15];
    const int* edge_index= (const int*)d_in[16];
    const int* node_type = (const int*)d_in[17];
    const int* edge_type = (const int*)d_in[18];
    float* out = (float*)d_out;

    int n = in_sizes[0] / D_;
    int e = in_sizes[16] / 2;
    int nb = (n + 1023) / 1024;
    int n32 = n * 32;

    int tot = n32 + 4*49152 + 1152 + 2*8192 + 32 + n + PERM_SZ + 8 + NCHUNK;
    fused_init_kernel<<<(tot + 255)/256, 256>>>(x, Wk, bk, Wq, bq, Wv, bv,
                                                rel_pri, rel_att, rel_msg,
                                                n_alpha, r_alpha, W_up, n, n32);
    int p2tot = 393216 + 3072 + (e + 3)/4;
    prep2_kernel<<<(p2tot + 255)/256, 256>>>(edge_index, node_type, n, e);
    scan_kernel<<<nb, 1024>>>(nb, n);
    scatter_kernel<<<(((n > e ? n : e) + 3)/4 + 255)/256, 256>>>(edge_index, edge_type, node_type, n, e);

    int nt64 = (n + 3*127 + 63) / 64;
    gemm_kernel<<<dim3(nt64, 9), 256>>>();
    edge_kernel<<<(n + 7)/8, 256>>>(n);
    update_tc_kernel<<<nt64, 256>>>(x, b_up, gamma, beta, out);
}

// round 17
// speedup vs baseline: 1.1475x; 1.1475x over previous
#include <cuda_runtime.h>
#include <cuda_fp16.h>
#include <math.h>

#define D_    128
#define H_    8
#define DK_   16
#define T_    3
#define R_    4
#define MAXN  50048
#define MAXE  800000
#define PERM_SZ 50432   // fits n + 3*127, 128-aligned
#define NCHUNK 64
#define GEMM_SMEM (2*128*136*2 + 128*4 + 128*4)

// ------------------------- device scratch -------------------------
// Combined GEMM weights: [t][1152 outs][128 in] fp16. Outs: [k(128) | qt r0..3 (512) | mt r0..3 (512)]
static __device__ __align__(16) __half g_W2[3*1152*128];
static __device__ __align__(16) float  g_b2[3*1152];
static __device__ __align__(16) float  g_Wf[2*3*16384];   // WeffqT, WeffvT fp32 [t][o][d]  (TRANSPOSED)
static __device__ __align__(16) float  g_bqv[2*3*128];    // bq_eff, bv_eff
static __device__ __align__(16) float  g_A [R_*H_*DK_*DK_]; // [r][h][d][o]
static __device__ __align__(16) float  g_M [R_*H_*DK_*DK_];
static __device__ float g_pri4[R_*H_];
static __device__ __align__(16) __half g_Wup_h[3*16384];  // [t][o][d] transposed fp16
static __device__ __align__(16) __half g_x_h [MAXN*D_];
static __device__ __align__(16) __half g_k_h [MAXN*D_];
static __device__ __align__(16) __half g_qt_h[MAXN*R_*D_]; // [n][r][h][d] pri-scaled
static __device__ __align__(16) __half g_mt_h[MAXN*R_*D_]; // [n][r][h][o]
static __device__ __align__(16) __half g_ge_h[MAXN*D_];    // half(gelu(attn))
static __device__ int g_deg[MAXN];
static __device__ int g_rowoff[MAXN+1];   // FINAL offsets after scan
static __device__ int g_pos[MAXE];        // per-edge within-node position (from count)
static __device__ int g_bflagsum[NCHUNK]; // chunk total + 1 (0 = not ready)
static __device__ int g_se[MAXE];          // (src<<2)|rel
static __device__ int g_perm[PERM_SZ];
static __device__ int g_tcount[8];
static __device__ int g_ncursor[8];
static __device__ int g_toff[8];

// ------------------------- helpers -------------------------
__device__ __forceinline__ void softmax2(float a0, float a1, float &o0, float &o1){
    float m  = fmaxf(a0, a1);
    float e0 = __expf(a0 - m), e1 = __expf(a1 - m);
    float inv = 1.0f / (e0 + e1);
    o0 = e0 * inv; o1 = e1 * inv;
}

__device__ __forceinline__ float gelu_t(float x){
    float x3 = x * x * x;
    return 0.5f * x * (1.0f + tanhf(0.7978845608028654f * (x + 0.044715f * x3)));
}

__device__ __forceinline__ void mma16816(float c[4], unsigned a0, unsigned a1,
                                         unsigned a2, unsigned a3,
                                         unsigned b0, unsigned b1){
    asm volatile(
        "mma.sync.aligned.m16n8k16.row.col.f32.f16.f16.f32 "
        "{%0,%1,%2,%3}, {%4,%5,%6,%7}, {%8,%9}, {%0,%1,%2,%3};"
        : "+f"(c[0]), "+f"(c[1]), "+f"(c[2]), "+f"(c[3])
        : "r"(a0), "r"(a1), "r"(a2), "r"(a3), "r"(b0), "r"(b1));
}

// ------------------------- fused init + x->fp16 + weights ---------
__global__ void fused_init_kernel(const float* __restrict__ x,
                            const float* __restrict__ Wk, const float* __restrict__ bk,
                            const float* __restrict__ Wq, const float* __restrict__ bq,
                            const float* __restrict__ Wv, const float* __restrict__ bv,
                            const float* __restrict__ rel_pri,
                            const float* __restrict__ rel_att,
                            const float* __restrict__ rel_msg,
                            const float* __restrict__ n_alpha,
                            const float* __restrict__ r_alpha,
                            const float* __restrict__ W_up,
                            int n, int n32){
    int g = blockIdx.x * blockDim.x + threadIdx.x;
    const int NW = 3*16384;   // 49152
    const int NB = 9*128;
    const int NA = R_*H_*256; // 8192

    if (g < n32){
        float4 v = ((const float4*)x)[g];
        __half2 h0 = __floats2half2_rn(v.x, v.y);
        __half2 h1 = __floats2half2_rn(v.z, v.w);
        ((uint2*)g_x_h)[g] = make_uint2(*(unsigned*)&h0, *(unsigned*)&h1);
        return;
    }
    g -= n32;
    if (g < NW){   // Weff_k -> g_W2 [t][o][d] fp16 (transposed)
        int t = g / 16384, j = g % 16384;
        int d = j >> 7, o = j & 127;
        float a0, a1; softmax2(n_alpha[t*2], n_alpha[t*2+1], a0, a1);
        g_W2[(t*1152 + o)*128 + d] = __float2half_rn(a0*Wk[j] + a1*Wk[16384 + j]);
        return;
    }
    g -= NW;
    if (g < NW){   // WeffqT fp32 [t][o][d]
        int t = g / 16384, rem = g % 16384;
        int o = rem >> 7, d = rem & 127;
        float a0, a1; softmax2(n_alpha[t*2], n_alpha[t*2+1], a0, a1);
        g_Wf[t*16384 + o*128 + d] = a0*Wq[d*128 + o] + a1*Wq[16384 + d*128 + o];
        return;
    }
    g -= NW;
    if (g < NW){   // WeffvT fp32 [t][o][d]
        int t = g / 16384, rem = g % 16384;
        int o = rem >> 7, d = rem & 127;
        float a0, a1; softmax2(n_alpha[t*2], n_alpha[t*2+1], a0, a1);
        g_Wf[3*16384 + t*16384 + o*128 + d] = a0*Wv[d*128 + o] + a1*Wv[16384 + d*128 + o];
        return;
    }
    g -= NW;
    if (g < NW){   // W_up transposed fp16
        int t = g / 16384, j = g % 16384;
        int d = j >> 7, o = j & 127;
        g_Wup_h[t*16384 + o*128 + d] = __float2half_rn(W_up[t*16384 + j]);
        return;
    }
    g -= NW;
    if (g < NB){
        int m = g / 384, rem = g % 384, t = rem / 128, c = rem % 128;
        float a0, a1; softmax2(n_alpha[t*2], n_alpha[t*2+1], a0, a1);
        const float* B = (m==0) ? bk : (m==1) ? bq : bv;
        float val = a0*B[c] + a1*B[128 + c];
        if (m == 0) g_b2[t*1152 + c] = val;
        else        g_bqv[((m-1)*3 + t)*128 + c] = val;
        return;
    }
    g -= NB;
    if (g < NA){
        int r = g / 2048, j = g % 2048;
        float b0, b1; softmax2(r_alpha[r*2], r_alpha[r*2+1], b0, b1);
        g_A[g] = b0*rel_att[j] + b1*rel_att[2048 + j];
        return;
    }
    g -= NA;
    if (g < NA){
        int r = g / 2048, j = g % 2048;
        float b0, b1; softmax2(r_alpha[r*2], r_alpha[r*2+1], b0, b1);
        g_M[g] = b0*rel_msg[j] + b1*rel_msg[2048 + j];
        return;
    }
    g -= NA;
    if (g < 32){
        int r = g/8, h = g%8;
        float b0, b1; softmax2(r_alpha[r*2], r_alpha[r*2+1], b0, b1);
        g_pri4[g] = (b0*rel_pri[h] + b1*rel_pri[8 + h]) * 0.25f;
        return;
    }
    g -= 32;
    if (g < n){ g_deg[g] = 0; return; }
    g -= n;
    if (g < PERM_SZ){ g_perm[g] = -1; return; }
    g -= PERM_SZ;
    if (g < 8){ g_tcount[g] = 0; g_ncursor[g] = 0; return; }
    g -= 8;
    if (g < NCHUNK) g_bflagsum[g] = 0;
}

// -- prep2: W2 qt/mt + folded biases + COUNT (positions saved) -----
__global__ void prep2_kernel(const int* __restrict__ ei, const int* __restrict__ ntype,
                             int n, int e){
    int g = blockIdx.x * blockDim.x + threadIdx.x;
    const int NW2 = 3*1024*128;  // 393216
    if (g < NW2){
        int t = g / 131072, rem = g % 131072;
        int col = rem >> 7, d = rem & 127;
        int part = col >> 9;
        int c = col & 511;
        int r = c >> 7, ho = c & 127, h = ho >> 4, j = ho & 15;
        const float* tab = part ? g_M : g_A;
        const float* Wf  = g_Wf + (part*3 + t)*16384 + (h*16)*128 + d;  // step 128 per i
        const float* ta  = tab + r*2048 + h*256 + (part ? j : j*16);
        int st = part ? 16 : 1;
        float s = 0.f;
        #pragma unroll
        for (int i = 0; i < 16; i++) s += ta[i*st] * Wf[i*128];
        if (!part) s *= g_pri4[r*8 + h];
        g_W2[(t*1152 + 128 + col)*128 + d] = __float2half_rn(s);
        return;
    }
    g -= NW2;
    if (g < 3072){
        int t = g / 1024, col = g % 1024;
        int part = col >> 9;
        int c = col & 511;
        int r = c >> 7, ho = c & 127, h = ho >> 4, j = ho & 15;
        const float* tab = part ? g_M : g_A;
        const float* bv  = g_bqv + (part*3 + t)*128 + h*16;
        const float* ta  = tab + r*2048 + h*256 + (part ? j : j*16);
        int st = part ? 16 : 1;
        float s = 0.f;
        #pragma unroll
        for (int i = 0; i < 16; i++) s += ta[i*st] * bv[i];
        if (!part) s *= g_pri4[r*8 + h];
        g_b2[t*1152 + 128 + col] = s;
        return;
    }
    g -= 3072;
    // ---- merged count: positions saved for atomic-free scatter ----
    int ecnt4 = (e + 3) >> 2;
    if (g < ecnt4){
        int g4 = g * 4;
        if (g4 + 3 < e){
            int4 d = *(const int4*)&ei[e + g4];
            int4 p;
            p.x = atomicAdd(&g_deg[d.x], 1);
            p.y = atomicAdd(&g_deg[d.y], 1);
            p.z = atomicAdd(&g_deg[d.z], 1);
            p.w = atomicAdd(&g_deg[d.w], 1);
            *(int4*)&g_pos[g4] = p;
        } else {
            for (int i = g4; i < e; i++) g_pos[i] = atomicAdd(&g_deg[ei[e + i]], 1);
        }
        unsigned act = __activemask();
        int lane = threadIdx.x & 31;
        #pragma unroll
        for (int j = 0; j < 4; j++){
            int i = g4 + j;
            int t = (i < n) ? ntype[i] : -1;
            unsigned mask = __match_any_sync(act, t);
            if (t >= 0){
                int leader = __ffs(mask) - 1;
                if (lane == leader) atomicAdd(&g_tcount[t], __popc(mask));
            }
        }
    }
}

// ---- single-pass scan with decoupled lookback, FINAL offsets -----
__global__ void scan_kernel(int nb, int n){
    __shared__ int wsum[32];
    __shared__ int chunkpref;
    int tid = threadIdx.x, lane = tid & 31, wid = tid >> 5;
    int b = blockIdx.x;
    int i = b * 1024 + tid;
    int v = (i < n) ? g_deg[i] : 0;
    int x = v;
    #pragma unroll
    for (int o = 1; o < 32; o <<= 1){
        int y = __shfl_up_sync(0xffffffffu, x, o);
        if (lane >= o) x += y;
    }
    if (lane == 31) wsum[wid] = x;
    __syncthreads();
    if (wid == 0){
        int s = wsum[lane];
        #pragma unroll
        for (int o = 1; o < 32; o <<= 1){
            int y = __shfl_up_sync(0xffffffffu, s, o);
            if (lane >= o) s += y;
        }
        wsum[lane] = s;
    }
    __syncthreads();
    int pre = (wid > 0) ? wsum[wid-1] : 0;
    int total = wsum[31];
    if (tid == 0) atomicExch(&g_bflagsum[b], total + 1);   // publish
    if (wid == 0){
        int mysum = 0;
        for (int j = lane; j < b; j += 32){
            int val;
            do { val = atomicAdd(&g_bflagsum[j], 0); } while (val == 0);
            mysum += val - 1;
        }
        #pragma unroll
        for (int o = 16; o > 0; o >>= 1)
            mysum += __shfl_xor_sync(0xffffffffu, mysum, o);
        if (lane == 0){
            chunkpref = mysum;
            if (b == nb - 1){
                g_rowoff[n] = mysum + total;
                g_toff[0] = 0;
                for (int t = 0; t < T_; t++)
                    g_toff[t+1] = g_toff[t] + ((g_tcount[t] + 127) & ~127);
            }
        }
    }
    __syncthreads();
    int cp = chunkpref;
    if (i < n) g_rowoff[i] = cp + pre + x - v;   // FINAL exclusive offset
}

// ------------- scatter: atomic-free via saved positions -----------
__global__ void scatter_kernel(const int* __restrict__ ei, const int* __restrict__ etype,
                               const int* __restrict__ ntype, int n, int e){
    int g4 = (blockIdx.x * 256 + threadIdx.x) * 4;
    if (g4 + 3 < e){
        int4 s = *(const int4*)&ei[g4];
        int4 d = *(const int4*)&ei[e + g4];
        int4 r = *(const int4*)&etype[g4];
        int4 p = *(const int4*)&g_pos[g4];
        g_se[g_rowoff[d.x] + p.x] = (s.x << 2) | r.x;
        g_se[g_rowoff[d.y] + p.y] = (s.y << 2) | r.y;
        g_se[g_rowoff[d.z] + p.z] = (s.z << 2) | r.z;
        g_se[g_rowoff[d.w] + p.w] = (s.w << 2) | r.w;
    } else if (g4 < e){
        for (int i = g4; i < e; i++){
            int d = ei[e + i];
            g_se[g_rowoff[d] + g_pos[i]] = (ei[i] << 2) | etype[i];
        }
    }
    int lane = threadIdx.x & 31;
    #pragma unroll
    for (int j = 0; j < 4; j++){
        int i = g4 + j;
        int t = (i < n) ? ntype[i] : 3;
        unsigned mask = __match_any_sync(0xffffffffu, t);
        if (i < n){
            int leader = __ffs(mask) - 1;
            int rank = __popc(mask & ((1u << lane) - 1));
            int base = 0;
            if (lane == leader) base = atomicAdd(&g_ncursor[t], __popc(mask));
            base = __shfl_sync(mask, base, leader);
            g_perm[g_toff[t] + base + rank] = i;
        }
    }
}

// -- GEMM: x -> k|qt|mt (128x128 tile, FULL-K stage, single sync) --
__global__ void __launch_bounds__(256) gemm_kernel(){
    int my = blockIdx.y;
    int base = blockIdx.x * 128;
    if (base >= g_toff[3]) return;
    int t = (base >= g_toff[2]) ? 2 : (base >= g_toff[1]) ? 1 : 0;
    const __half* __restrict__ W  = g_W2 + (t*1152 + my*128)*128;
    const float* __restrict__ bvec = g_b2 + t*1152 + my*128;

    extern __shared__ __half smem[];
    __half (*Xs)[136] = (__half(*)[136])smem;
    __half (*Wt)[136] = (__half(*)[136])(smem + 128*136);
    int*   rows = (int*)(smem + 2*128*136);
    float* bs   = (float*)(rows + 128);

    int tid = threadIdx.x;
    if (tid < 128) rows[tid] = g_perm[base + tid];
    else bs[tid-128] = bvec[tid-128];
    __syncthreads();

    // stage ALL of X and W (K=128) in one batched phase
    for (int c = tid; c < 2048; c += 256){
        int row = c >> 4, cg = c & 15;
        int nd = rows[row];
        uint4 v = (nd >= 0) ? *(const uint4*)&g_x_h[nd*128 + cg*8]
                            : make_uint4(0,0,0,0);
        *(uint4*)&Xs[row][cg*8] = v;
        *(uint4*)&Wt[row][cg*8] = *(const uint4*)&W[row*128 + cg*8];
    }
    __syncthreads();

    int lane = tid & 31, wid = tid >> 5;
    int wm = wid & 3, wn = wid >> 2;
    int gq = lane >> 2, tig = lane & 3;
    float acc[2][8][4] = {};

    #pragma unroll
    for (int kk = 0; kk < 128; kk += 16){
        unsigned a[2][4];
        #pragma unroll
        for (int mi = 0; mi < 2; mi++){
            int arow = wm*32 + mi*16 + gq;
            int acol = kk + tig*2;
            a[mi][0] = *(unsigned*)&Xs[arow][acol];
            a[mi][1] = *(unsigned*)&Xs[arow+8][acol];
            a[mi][2] = *(unsigned*)&Xs[arow][acol+8];
            a[mi][3] = *(unsigned*)&Xs[arow+8][acol+8];
        }
        #pragma unroll
        for (int nt = 0; nt < 8; nt++){
            int brow = wn*64 + nt*8 + gq;
            unsigned b0 = *(unsigned*)&Wt[brow][kk + tig*2];
            unsigned b1 = *(unsigned*)&Wt[brow][kk + 8 + tig*2];
            mma16816(acc[0][nt], a[0][0],a[0][1],a[0][2],a[0][3], b0, b1);
            mma16816(acc[1][nt], a[1][0],a[1][1],a[1][2],a[1][3], b0, b1);
        }
    }

    __half* outb; int stride;
    if (my == 0){ outb = g_k_h; stride = 128; }
    else if (my < 5){ outb = g_qt_h + (my-1)*128; stride = 512; }
    else { outb = g_mt_h + (my-5)*128; stride = 512; }

    #pragma unroll
    for (int nt = 0; nt < 8; nt++){
        int col = wn*64 + nt*8 + tig*2;
        float b0 = bs[col], b1 = bs[col+1];
        #pragma unroll
        for (int mi = 0; mi < 2; mi++){
            #pragma unroll
            for (int rr = 0; rr < 2; rr++){
                int row = wm*32 + mi*16 + gq + rr*8;
                int nd = rows[row];
                if (nd < 0) continue;
                __half2 h2 = __floats2half2_rn(acc[mi][nt][rr*2] + b0,
                                               acc[mi][nt][rr*2+1] + b1);
                *(__half2*)&outb[nd*stride + col] = h2;
            }
        }
    }
}

// ------------------------- edge: warp/dst, no-max softmax ---------
__global__ void __launch_bounds__(256) edge_kernel(int n){
    int node = blockIdx.x*8 + (threadIdx.x >> 5);
    if (node >= n) return;
    int lane = threadIdx.x & 31;
    int h = lane >> 2, dq = lane & 3;
    int koff = h*16 + dq*4;

    float4 qt[4];
    #pragma unroll
    for (int r = 0; r < 4; r++){
        uint2 qa = *(const uint2*)&g_qt_h[node*512 + r*128 + koff];
        float2 lo = __half22float2(*(__half2*)&qa.x);
        float2 hi = __half22float2(*(__half2*)&qa.y);
        qt[r] = make_float4(lo.x, lo.y, hi.x, hi.y);
    }

    int beg = g_rowoff[node], end = g_rowoff[node+1];
    float s = 0.f;
    float4 acc = {0,0,0,0};

    int se0 = 0, se1 = 0;
    uint2 k0 = {0,0}, k1 = {0,0}, mm0 = {0,0}, mm1 = {0,0};
    if (beg < end){
        se0 = g_se[beg]; int sr = se0 >> 2, r = se0 & 3;
        k0  = *(const uint2*)&g_k_h [sr*128 + koff];
        mm0 = *(const uint2*)&g_mt_h[sr*512 + r*128 + koff];
    }
    if (beg + 1 < end){
        se1 = g_se[beg+1]; int sr = se1 >> 2, r = se1 & 3;
        k1  = *(const uint2*)&g_k_h [sr*128 + koff];
        mm1 = *(const uint2*)&g_mt_h[sr*512 + r*128 + koff];
    }

    for (int o = beg; o < end; o += 2){
        int nse0 = 0, nse1 = 0;
        uint2 nk0 = {0,0}, nk1 = {0,0}, nm0 = {0,0}, nm1 = {0,0};
        if (o + 2 < end){
            nse0 = g_se[o+2]; int sr = nse0 >> 2, r = nse0 & 3;
            nk0 = *(const uint2*)&g_k_h [sr*128 + koff];
            nm0 = *(const uint2*)&g_mt_h[sr*512 + r*128 + koff];
        }
        if (o + 3 < end){
            nse1 = g_se[o+3]; int sr = nse1 >> 2, r = nse1 & 3;
            nk1 = *(const uint2*)&g_k_h [sr*128 + koff];
            nm1 = *(const uint2*)&g_mt_h[sr*512 + r*128 + koff];
        }
        {
            int r = se0 & 3;
            float2 ka = __half22float2(*(__half2*)&k0.x);
            float2 kb = __half22float2(*(__half2*)&k0.y);
            float4 q4 = qt[r];
            float p = ka.x*q4.x + ka.y*q4.y + kb.x*q4.z + kb.y*q4.w;
            p += __shfl_xor_sync(0xffffffffu, p, 1);
            p += __shfl_xor_sync(0xffffffffu, p, 2);
            float e = __expf(fminf(p, 60.f));
            float2 ma = __half22float2(*(__half2*)&mm0.x);
            float2 mb = __half22float2(*(__half2*)&mm0.y);
            s += e;
            acc.x += e*ma.x; acc.y += e*ma.y;
            acc.z += e*mb.x; acc.w += e*mb.y;
        }
        if (o + 1 < end){
            int r = se1 & 3;
            float2 ka = __half22float2(*(__half2*)&k1.x);
            float2 kb = __half22float2(*(__half2*)&k1.y);
            float4 q4 = qt[r];
            float p = ka.x*q4.x + ka.y*q4.y + kb.x*q4.z + kb.y*q4.w;
            p += __shfl_xor_sync(0xffffffffu, p, 1);
            p += __shfl_xor_sync(0xffffffffu, p, 2);
            float e = __expf(fminf(p, 60.f));
            float2 ma = __half22float2(*(__half2*)&mm1.x);
            float2 mb = __half22float2(*(__half2*)&mm1.y);
            s += e;
            acc.x += e*ma.x; acc.y += e*ma.y;
            acc.z += e*mb.x; acc.w += e*mb.y;
        }
        se0 = nse0; k0 = nk0; mm0 = nm0;
        se1 = nse1; k1 = nk1; mm1 = nm1;
    }
    float inv = 1.0f / (s + 1e-16f);
    __half2 h0 = __floats2half2_rn(gelu_t(acc.x*inv), gelu_t(acc.y*inv));
    __half2 h1 = __floats2half2_rn(gelu_t(acc.z*inv), gelu_t(acc.w*inv));
    *(uint2*)&g_ge_h[node*128 + koff] = make_uint2(*(unsigned*)&h0, *(unsigned*)&h1);
}

// ------------------------- tensor-core update + residual + LN -----
__global__ void __launch_bounds__(256) update_tc_kernel(
        const float* __restrict__ x, const float* __restrict__ bup,
        const float* __restrict__ gamma, const float* __restrict__ beta,
        float* __restrict__ out){
    int base = blockIdx.x * 64;
    if (base >= g_toff[3]) return;
    int t = (base >= g_toff[2]) ? 2 : (base >= g_toff[1]) ? 1 : 0;
    const __half* __restrict__ W = g_Wup_h + t*16384;

    __shared__ union {
        struct { __half Xs[64][136]; __half Wt[128][72]; } s;
        float Cs[64][132];
    } u;
    __shared__ int rows[64];
    __shared__ float bs[128];

    int tid = threadIdx.x;
    if (tid < 64) rows[tid] = g_perm[base + tid];
    if (tid >= 128 && tid < 256) bs[tid-128] = bup[t*128 + tid-128];
    __syncthreads();

    for (int c = tid; c < 1024; c += 256){
        int row = c >> 4, cg = c & 15;
        int nd = rows[row];
        uint4 v = (nd >= 0) ? *(const uint4*)&g_ge_h[nd*128 + cg*8]
                            : make_uint4(0,0,0,0);
        *(uint4*)&u.s.Xs[row][cg*8] = v;
    }

    int lane = tid & 31, wid = tid >> 5;
    int wm = wid & 3, wn = wid >> 2;
    int gq = lane >> 2, tig = lane & 3;
    float acc[8][4] = {};

    for (int kp = 0; kp < 128; kp += 64){
        __syncthreads();
        for (int c = tid; c < 1024; c += 256){
            int nrow = c >> 3, cg = c & 7;
            *(uint4*)&u.s.Wt[nrow][cg*8] = *(const uint4*)&W[nrow*128 + kp + cg*8];
        }
        __syncthreads();
        #pragma unroll
        for (int kk = 0; kk < 64; kk += 16){
            int arow = wm*16 + gq;
            int acol = kp + kk + tig*2;
            unsigned a0 = *(unsigned*)&u.s.Xs[arow][acol];
            unsigned a1 = *(unsigned*)&u.s.Xs[arow+8][acol];
            unsigned a2 = *(unsigned*)&u.s.Xs[arow][acol+8];
            unsigned a3 = *(unsigned*)&u.s.Xs[arow+8][acol+8];
            #pragma unroll
            for (int nt = 0; nt < 8; nt++){
                int brow = wn*64 + nt*8 + gq;
                unsigned b0 = *(unsigned*)&u.s.Wt[brow][kk + tig*2];
                unsigned b1 = *(unsigned*)&u.s.Wt[brow][kk + 8 + tig*2];
                mma16816(acc[nt], a0, a1, a2, a3, b0, b1);
            }
        }
    }
    __syncthreads();
    #pragma unroll
    for (int nt = 0; nt < 8; nt++){
        int col = wn*64 + nt*8 + tig*2;
        float b0 = bs[col], b1 = bs[col+1];
        #pragma unroll
        for (int rr = 0; rr < 2; rr++){
            int row = wm*16 + gq + rr*8;
            u.Cs[row][col]   = acc[nt][rr*2]   + b0;
            u.Cs[row][col+1] = acc[nt][rr*2+1] + b1;
        }
    }
    __syncthreads();

    int tx = tid & 31, ty = tid >> 5;
    float4 g4 = *(const float4*)&gamma[t*128 + tx*4];
    float4 e4 = *(const float4*)&beta [t*128 + tx*4];
    #pragma unroll
    for (int i = 0; i < 8; i++){
        int row = ty*8 + i;
        int nd = rows[row];
        if (nd < 0) continue;
        float4 cv = *(float4*)&u.Cs[row][tx*4];
        float4 xi = *(const float4*)&x[nd*128 + tx*4];
        float v0 = cv.x + xi.x, v1 = cv.y + xi.y;
        float v2 = cv.z + xi.z, v3 = cv.w + xi.w;
        float sum = v0+v1+v2+v3;
        float sq  = v0*v0+v1*v1+v2*v2+v3*v3;
        #pragma unroll
        for (int o = 16; o > 0; o >>= 1){
            sum += __shfl_xor_sync(0xffffffffu, sum, o);
            sq  += __shfl_xor_sync(0xffffffffu, sq,  o);
        }
        float mu = sum * (1.0f/128.0f);
        float var = sq * (1.0f/128.0f) - mu*mu;
        float rstd = rsqrtf(var + 1e-5f);
        float4 o4;
        o4.x = (v0-mu)*rstd*g4.x + e4.x;
        o4.y = (v1-mu)*rstd*g4.y + e4.y;
        o4.z = (v2-mu)*rstd*g4.z + e4.z;
        o4.w = (v3-mu)*rstd*g4.w + e4.w;
        *(float4*)&out[nd*128 + tx*4] = o4;
    }
}

// ------------------------- launch ---------------------------------
extern "C" void kernel_launch(void* const* d_in, const int* in_sizes, int n_in,
                              void* d_out, int out_size) {
    const float* x       = (const float*)d_in[0];
    const float* Wk      = (const float*)d_in[1];
    const float* bk      = (const float*)d_in[2];
    const float* Wq      = (const float*)d_in[3];
    const float* bq      = (const float*)d_in[4];
    const float* Wv      = (const float*)d_in[5];
    const float* bv      = (const float*)d_in[6];
    const float* rel_pri = (const float*)d_in[7];
    const float* rel_att = (const float*)d_in[8];
    const float* rel_msg = (const float*)d_in[9];
    const float* n_alpha = (const float*)d_in[10];
    const float* r_alpha = (const float*)d_in[11];
    const float* W_up    = (const float*)d_in[12];
    const float* b_up    = (const float*)d_in[13];
    const float* gamma   = (const float*)d_in[14];
    const float* beta    = (const float*)d_in[15];
    const int* edge_index= (const int*)d_in[16];
    const int* node_type = (const int*)d_in[17];
    const int* edge_type = (const int*)d_in[18];
    float* out = (float*)d_out;

    int n = in_sizes[0] / D_;
    int e = in_sizes[16] / 2;
    int nb = (n + 1023) / 1024;
    int n32 = n * 32;

    static int smem_set = 0;
    if (!smem_set){
        cudaFuncSetAttribute(gemm_kernel,
                             cudaFuncAttributeMaxDynamicSharedMemorySize, GEMM_SMEM);
        smem_set = 1;
    }

    int tot = n32 + 4*49152 + 1152 + 2*8192 + 32 + n + PERM_SZ + 8 + NCHUNK;
    fused_init_kernel<<<(tot + 255)/256, 256>>>(x, Wk, bk, Wq, bq, Wv, bv,
                                                rel_pri, rel_att, rel_msg,
                                                n_alpha, r_alpha, W_up, n, n32);
    int p2tot = 393216 + 3072 + (e + 3)/4;
    prep2_kernel<<<(p2tot + 255)/256, 256>>>(edge_index, node_type, n, e);
    scan_kernel<<<nb, 1024>>>(nb, n);
    scatter_kernel<<<(((n > e ? n : e) + 3)/4 + 255)/256, 256>>>(edge_index, edge_type, node_type, n, e);

    int nt128 = (n + 3*127 + 127) / 128;
    int nt64  = (n + 3*127 + 63) / 64;
    gemm_kernel<<<dim3(nt128, 9), 256, GEMM_SMEM>>>();
    edge_kernel<<<(n + 7)/8, 256>>>(n);
    update_tc_kernel<<<nt64, 256>>>(x, b_up, gamma, beta, out);
}